// round 14
// baseline (speedup 1.0000x reference)
#include <cuda_runtime.h>

// ---------------------------------------------------------------------------
// SparseWindowPartitionLayer — full GPU pipeline, graph-capturable, no CUB.
//   win id < 16810; T=16/32/48 by pre-drop window count; FEAT_DIM=192
//   pe depends only on in-window coords => 400-row LUT (L2 resident)
//   Stable per-window order: rank-from-histogram scatter (NO scatter atomics),
//   then per-window warp bitonic sort by original voxel index.
//   Drops need pre-drop cnt>48 (≈5σ at λ≈23) => almost never. Dropped voxel
//   ids go to a tiny list; the feats writer maps pos->src by least-fixpoint
//   over that list (identity when empty). No global compaction pass at all.
//   meta (2 blocks) is fused into the writer launch; only pe blocks (late
//   waves) wait on its done-flag.
// ---------------------------------------------------------------------------

#define NV    300000
#define WMAX  16810
#define DCAP  4096

__device__ int2 g_W[NV];                        // (w0, w1)
__device__ int  g_tb[NV];                       // tb0 | tb1<<16
__device__ int2 g_rank[NV];                     // (rank in w0, rank in w1-spec)
__device__ int  g_arrA[NV], g_arrB[NV];         // window-grouped voxel ids
__device__ int  g_keepF[NV];
__device__ int  g_cnt0[WMAX], g_cnt1[WMAX];     // cnt1 = speculative (pre-drop)
__device__ int  g_cnt1c[WMAX], g_cntF0[WMAX];   // corrected counts
__device__ int  g_startA[WMAX], g_startB[WMAX]; // pure exclusive scans
__device__ int  g_lvl0[WMAX], g_lvl1[WMAX], g_conti0[WMAX], g_conti1[WMAX];
__device__ int  g_nwin[6], g_total, g_done, g_scanDone, g_offDone;
__device__ int  g_dropCnt, g_dropList[DCAP];
__device__ long long g_off[16];
__device__ float g_tab[400 * 192];

__device__ __forceinline__ int targetOf(int c) { return c < 16 ? 16 : (c < 32 ? 32 : 48); }
__device__ __forceinline__ int levelOf(int c)  { return c < 16 ? 0  : (c < 32 ? 1  : 2);  }
__device__ __forceinline__ int tokensOf(int l) { return l == 2 ? 48 : (16 << l); }

// ---- pe LUT + zero counters/status -------------------------------------------
__global__ void k_tab() {
    int t = blockIdx.x * blockDim.x + threadIdx.x;
    if (t < WMAX) { g_cnt0[t] = 0; g_cnt1[t] = 0; }
    if (t == 0)   { g_done = 0; g_scanDone = 0; g_offDone = 0; g_dropCnt = 0; }
    if (t >= 400 * 192) return;
    int row = t / 192, f = t - 192 * row;
    int cx = row % 10, cy = (row / 10) % 10, cz = row / 100;
    int axis = f / 64, k = f - 64 * axis;
    int j = k >> 1, ph = k & 1;
    float v = (axis == 0) ? (float)(cx - 5)
            : (axis == 1) ? (float)(cy - 5)
                          : (float)(cz - 2);
    float invf = (float)exp(log(1000.0) * (double)j / 32.0);
    float e = v / invf;
    g_tab[t] = ph ? cosf(e) : sinf(e);
}

// ---- window ids + histograms + ranks + tb + keepF ------------------------------
__global__ void k_wins(const int* __restrict__ coords, int n) {
    int i = blockIdx.x * blockDim.x + threadIdx.x;
    if (i >= n) return;
    int4 c = ((const int4*)coords)[i];      // (b, z, y, x)
    int b = c.x, z = c.y, y = c.z, x = c.w;
    int w0 = b * 8405 + ((x + 10) / 10) * 205 + ((y + 10) / 10) * 5 + ((z + 4) / 4);
    int w1 = b * 8405 + ((x + 5)  / 10) * 205 + ((y + 5)  / 10) * 5 + ((z + 2) / 4);
    g_W[i] = make_int2(w0, w1);
    int tb0 = ((z % 4) * 10 + (y % 10)) * 10 + (x % 10);
    int tb1 = (((z + 2) % 4) * 10 + ((y + 5) % 10)) * 10 + ((x + 5) % 10);
    g_tb[i] = tb0 | (tb1 << 16);
    g_keepF[i] = 1;
    int r0 = atomicAdd(&g_cnt0[w0], 1);
    int r1 = atomicAdd(&g_cnt1[w1], 1);     // speculative rank (pre-drop)
    g_rank[i] = make_int2(r0, r1);
}

// ---- 1024-thread exclusive scan over WMAX counters (+input copy) ----------------
__device__ void exscan_body(const int* __restrict__ in, int* __restrict__ out,
                            int* __restrict__ cpy) {
    __shared__ int ws[32];
    int tid = threadIdx.x, lane = tid & 31, warp = tid >> 5;
    int carry = 0;
    for (int base = 0; base < WMAX; base += 1024) {
        int w = base + tid;
        int v = (w < WMAX) ? in[w] : 0;
        if (w < WMAX) cpy[w] = v;
        int x = v;
        #pragma unroll
        for (int o = 1; o < 32; o <<= 1) { int y = __shfl_up_sync(~0u, x, o); if (lane >= o) x += y; }
        if (lane == 31) ws[warp] = x;
        __syncthreads();
        if (warp == 0) {
            int y = ws[lane];
            #pragma unroll
            for (int o = 1; o < 32; o <<= 1) { int z = __shfl_up_sync(~0u, y, o); if (lane >= o) y += z; }
            ws[lane] = y;
        }
        __syncthreads();
        int excl = x - v + (warp ? ws[warp - 1] : 0) + carry;
        if (w < WMAX) out[w] = excl;
        carry += ws[31];
        __syncthreads();
    }
}

// ---- fused: blocks 0,1 = dual exscan (producers); rest = scatter (consumers) ----
__global__ void k_scanscat(int n) {
    if (blockIdx.x < 2) {
        if (blockIdx.x == 0) exscan_body(g_cnt0, g_startA, g_cntF0);
        else                 exscan_body(g_cnt1, g_startB, g_cnt1c);
        __syncthreads();
        if (threadIdx.x == 0) {
            __threadfence();
            atomicAdd(&g_scanDone, 1);
        }
        return;
    }
    int i = (blockIdx.x - 2) * blockDim.x + threadIdx.x;
    int2 w = make_int2(0, 0), r = make_int2(0, 0);
    bool valid = (i < n);
    if (valid) { w = g_W[i]; r = g_rank[i]; }   // prefetch overlaps the scans
    if (threadIdx.x == 0) {
        while (atomicAdd(&g_scanDone, 0) < 2) __nanosleep(200);
    }
    __syncthreads();
    __threadfence();                            // acquire scan outputs
    if (valid) {
        g_arrA[g_startA[w.x] + r.x] = i;
        g_arrB[g_startB[w.y] + r.y] = i;
    }
}

// ---- register bitonic sort over 32*R elements ------------------------------------
template <int R>
__device__ __forceinline__ void bitonicReg(int (&v)[R], int lane) {
    const int NE = 32 * R;
    #pragma unroll
    for (int k = 2; k <= NE; k <<= 1) {
        #pragma unroll
        for (int j = k >> 1; j > 0; j >>= 1) {
            if (j >= 32) {
                int s = j >> 5;
                #pragma unroll
                for (int r = 0; r < R; r++) {
                    int pr = r ^ s;
                    if (r < pr) {
                        bool up = (((lane + 32 * r) & k) == 0);
                        int x = v[r], y = v[pr];
                        int lo = min(x, y), hi = max(x, y);
                        v[r]  = up ? lo : hi;
                        v[pr] = up ? hi : lo;
                    }
                }
            } else {
                #pragma unroll
                for (int r = 0; r < R; r++) {
                    int e = lane + 32 * r;
                    bool up = ((e & k) == 0);
                    int o = __shfl_xor_sync(~0u, v[r], j);
                    bool lower = ((lane & j) == 0);
                    int mn = min(v[r], o), mx = max(v[r], o);
                    v[r] = (up == lower) ? mn : mx;
                }
            }
        }
    }
}

template <int R>
__device__ __forceinline__ void sortReg(int* a, int cnt, int lane) {
    int v[R];
    #pragma unroll
    for (int r = 0; r < R; r++) {
        int e = lane + 32 * r;
        v[r] = (e < cnt) ? a[e] : 0x7FFFFFFF;
    }
    // fast path: skip network + store when already sorted
    bool ok = true;
    #pragma unroll
    for (int r = 0; r < R; r++) {
        int p = __shfl_up_sync(~0u, v[r], 1);
        if (lane > 0) ok &= (v[r] >= p);
        if (r > 0) {
            int l31 = __shfl_sync(~0u, v[r - 1], 31);
            if (lane == 0) ok &= (v[r] >= l31);
        }
    }
    if (__all_sync(~0u, ok)) return;
    bitonicReg<R>(v, lane);
    #pragma unroll
    for (int r = 0; r < R; r++) {
        int e = lane + 32 * r;
        if (e < cnt) a[e] = v[r];
    }
}

__device__ void sortSeg(int* a, int cnt, int lane) {
    if (cnt <= 32)       sortReg<1>(a, cnt, lane);
    else if (cnt <= 64)  sortReg<2>(a, cnt, lane);
    else if (cnt <= 128) sortReg<4>(a, cnt, lane);
    else {
        // robust fallback (not expected for this dataset): odd-even transposition
        for (int pass = 0; pass < cnt; pass++) {
            for (int p = (pass & 1) + 2 * lane; p + 1 < cnt; p += 64) {
                int x = a[p], y = a[p + 1];
                if (x > y) { a[p] = y; a[p + 1] = x; }
            }
            __syncwarp();
            __threadfence_block();
        }
    }
    __syncwarp();
}

// ---- shift-0 sort; drops: flag+list, fix counts, sentinel the arrB slot ----------
__global__ void k_sw0() {
    int wid = blockIdx.x * (blockDim.x >> 5) + (threadIdx.x >> 5);
    if (wid >= WMAX) return;
    int lane = threadIdx.x & 31;
    int cnt = g_cnt0[wid];
    if (cnt == 0) return;
    int seg = g_startA[wid];
    sortSeg(g_arrA + seg, cnt, lane);
    int t = targetOf(cnt);
    for (int e = t + lane; e < cnt; e += 32) {   // drops only (rare)
        int v = g_arrA[seg + e];
        g_keepF[v] = 0;
        int slot = atomicAdd(&g_dropCnt, 1);
        if (slot < DCAP) g_dropList[slot] = v;
        int w1 = g_W[v].y;
        atomicSub(&g_cnt1c[w1], 1);
        atomicSub(&g_cntF0[wid], 1);
        g_arrB[g_startB[w1] + g_rank[v].y] = 0x7FFFFFFF;  // sentinel
    }
}

// ---- shift-1 sort (sentinels go to tail); drops among first cnt1c entries --------
__global__ void k_sw1() {
    int wid = blockIdx.x * (blockDim.x >> 5) + (threadIdx.x >> 5);
    if (wid >= WMAX) return;
    int lane = threadIdx.x & 31;
    int spec = g_cnt1[wid];
    if (spec == 0) return;
    int seg = g_startB[wid];
    sortSeg(g_arrB + seg, spec, lane);
    int cnt = g_cnt1c[wid];                      // exact kept0 count
    int t = targetOf(cnt);
    for (int e = t + lane; e < cnt; e += 32) {   // drops only (rare)
        int v = g_arrB[seg + e];
        g_keepF[v] = 0;
        int slot = atomicAdd(&g_dropCnt, 1);
        if (slot < DCAP) g_dropList[slot] = v;
        atomicSub(&g_cntF0[g_W[v].x], 1);
    }
}

// ---- meta body (one block per shift, 256 threads): lvl/conti, nwin, offsets ------
__device__ void meta_body(int s) {
    __shared__ int sh0[8], sh1[8], sh2[8], sh3[8];
    int tid = threadIdx.x, lane = tid & 31, warp = tid >> 5;
    int* lvlArr  = s ? g_lvl1   : g_lvl0;
    int* contArr = s ? g_conti1 : g_conti0;
    int c0 = 0, c1 = 0, c2 = 0, c3 = 0;
    for (int base = 0; base < WMAX; base += 1024) {
        int cf[4], lv[4], f1[4], f2[4], f3[4];
        #pragma unroll
        for (int k = 0; k < 4; k++) {
            int w = base + tid * 4 + k;
            cf[k] = 0; lv[k] = 0;
            if (w < WMAX) {
                if (s == 0) { cf[k] = g_cntF0[w]; lv[k] = levelOf(g_cnt0[w]); }
                else        { int c = g_cnt1c[w]; cf[k] = min(c, targetOf(c)); lv[k] = levelOf(c); }
            }
            int occ = cf[k] > 0;
            f1[k] = (occ && lv[k] == 0) ? 1 : 0;
            f2[k] = (occ && lv[k] == 1) ? 1 : 0;
            f3[k] = (occ && lv[k] == 2) ? 1 : 0;
        }
        int t0 = cf[0] + cf[1] + cf[2] + cf[3];
        int t1 = f1[0] + f1[1] + f1[2] + f1[3];
        int t2 = f2[0] + f2[1] + f2[2] + f2[3];
        int t3 = f3[0] + f3[1] + f3[2] + f3[3];
        int x0 = t0, x1 = t1, x2 = t2, x3 = t3;
        #pragma unroll
        for (int o = 1; o < 32; o <<= 1) {
            int y0 = __shfl_up_sync(~0u, x0, o);
            int y1 = __shfl_up_sync(~0u, x1, o);
            int y2 = __shfl_up_sync(~0u, x2, o);
            int y3 = __shfl_up_sync(~0u, x3, o);
            if (lane >= o) { x0 += y0; x1 += y1; x2 += y2; x3 += y3; }
        }
        if (lane == 31) { sh0[warp] = x0; sh1[warp] = x1; sh2[warp] = x2; sh3[warp] = x3; }
        __syncthreads();
        if (tid < 8) {
            int y0 = sh0[tid], y1 = sh1[tid], y2 = sh2[tid], y3 = sh3[tid];
            #pragma unroll
            for (int o = 1; o < 8; o <<= 1) {
                int z0 = __shfl_up_sync(0xFFu, y0, o);
                int z1 = __shfl_up_sync(0xFFu, y1, o);
                int z2 = __shfl_up_sync(0xFFu, y2, o);
                int z3 = __shfl_up_sync(0xFFu, y3, o);
                if (tid >= o) { y0 += z0; y1 += z1; y2 += z2; y3 += z3; }
            }
            sh0[tid] = y0; sh1[tid] = y1; sh2[tid] = y2; sh3[tid] = y3;
        }
        __syncthreads();
        int b1 = x1 - t1 + (warp ? sh1[warp - 1] : 0) + c1;
        int b2 = x2 - t2 + (warp ? sh2[warp - 1] : 0) + c2;
        int b3 = x3 - t3 + (warp ? sh3[warp - 1] : 0) + c3;
        #pragma unroll
        for (int k = 0; k < 4; k++) {
            int w = base + tid * 4 + k;
            if (w < WMAX) {
                lvlArr[w]  = lv[k];
                contArr[w] = (lv[k] == 0) ? b1 : (lv[k] == 1) ? b2 : b3;
            }
            b1 += f1[k]; b2 += f2[k]; b3 += f3[k];
        }
        c0 += sh0[7]; c1 += sh1[7]; c2 += sh2[7]; c3 += sh3[7];
        __syncthreads();
    }
    if (tid == 0) {
        g_nwin[3 * s + 0] = c1;
        g_nwin[3 * s + 1] = c2;
        g_nwin[3 * s + 2] = c3;
        if (s == 0) g_total = c0;
        __threadfence();
        int prev = atomicAdd(&g_done, 1);
        if (prev == 1) {                       // second finisher computes offsets
            __threadfence();
            long long M = *((volatile int*)&g_total);
            int nw[6];
            #pragma unroll
            for (int q = 0; q < 6; q++) nw[q] = *((volatile int*)&g_nwin[q]);
            long long o = 0;
            g_off[0] = 0;       o = M * 192;          // feats
            g_off[1] = o;       o += M * 4;           // coords
            const int T[3] = {16, 32, 48};
            for (int ss = 0; ss < 2; ss++) {
                for (int d = 0; d < 3; d++) { g_off[2 + 6 * ss + d] = o; o += (long long)nw[3 * ss + d] * T[d] * 192; }
                for (int d = 0; d < 3; d++) { g_off[5 + 6 * ss + d] = o; o += (long long)nw[3 * ss + d] * T[d]; }
            }
            g_off[14] = o;
            __threadfence();
            *((volatile int*)&g_offDone) = 1;
        }
    }
}

// ---- fused writer: meta (blocks 0,1), feats+coords, pe+mask ----------------------
__global__ void k_write(const float4* __restrict__ fin, const int* __restrict__ coords,
                        float* __restrict__ out, int featBlocks, int n) {
    if (blockIdx.x < 2) {                      // meta producers (wave-1 resident)
        meta_body(blockIdx.x);
        return;
    }
    int bI = (int)blockIdx.x - 2;

    if (bI < featBlocks) {
        // ---- feats + coords: pos->src via tiny drop list (identity when empty)
        int d = *((volatile int*)&g_dropCnt);  // final before this launch
        if (d > DCAP) d = DCAP;
        int M = n - d;
        int idx = bI * blockDim.x + threadIdx.x;
        int pos = idx / 48, c = idx - 48 * pos;
        if (pos >= M) return;
        int src = pos;
        if (d > 0) {                            // least fixpoint src = pos + |D<=src|
            int prev = -1;
            while (src != prev) {
                prev = src;
                int cdl = 0;
                for (int q = 0; q < d; q++) cdl += (g_dropList[q] <= src);
                src = pos + cdl;
            }
        }
        float4 v = __ldcs(&fin[(long long)src * 48 + c]);
        __stcs(&((float4*)out)[(long long)pos * 48 + c], v);
        if (c == 0) {
            int4 cc = ((const int4*)coords)[src];
            float4* oc = (float4*)(out + (long long)M * 192);
            __stcs(&oc[pos], make_float4((float)cc.x, (float)cc.y, (float)cc.z, (float)cc.w));
        }
        return;
    }

    // ---- pe + mask: one block per (shift, window)
    int b = bI - featBlocks;                   // [0, 2*WMAX)
    int s = (b >= WMAX) ? 1 : 0;
    int w = b - s * WMAX;

    int cntSeg, cntF, segStart;
    const int* arr;
    if (s == 0) {
        cntSeg = g_cnt0[w];
        cntF   = g_cntF0[w];
        if (cntF == 0) return;
        segStart = g_startA[w];
        arr = g_arrA;
    } else {
        int cnt = g_cnt1c[w];
        if (cnt <= 0) return;
        cntF = min(cnt, targetOf(cnt));
        segStart = g_startB[w];
        arr = g_arrB;
        cntSeg = cntF;        // first cntF sorted entries are the kept set
    }

    // wait for meta outputs (lvl/conti/off); zero-cost in late waves
    if (threadIdx.x == 0) {
        while (*((volatile int*)&g_offDone) == 0) __nanosleep(100);
    }
    __syncthreads();
    __threadfence();

    int lvl   = s ? g_lvl1[w]   : g_lvl0[w];
    int conti = s ? g_conti1[w] : g_conti0[w];
    int T = tokensOf(lvl);
    long long pebase   = g_off[2 + 6 * s + lvl] + (long long)conti * T * 192;
    long long maskbase = g_off[5 + 6 * s + lvl] + (long long)conti * T;

    __shared__ int rowtab[48];
    int t = threadIdx.x;
    if (t < 32) {
        int lane = t;
        int nk = 0;
        for (int base = 0; base < cntSeg; base += 32) {
            int r = base + lane;
            int v = (r < cntSeg) ? arr[segStart + r] : -1;
            int f = (v >= 0) ? ((s == 0) ? g_keepF[v] : 1) : 0;
            unsigned m = __ballot_sync(~0u, f);
            if (f) {
                int slot = nk + __popc(m & ((1u << lane) - 1));
                int tb = g_tb[v];
                rowtab[slot] = s ? (tb >> 16) : (tb & 0xFFFF);
            }
            nk += __popc(m);
        }
        for (int p = nk + lane; p < T; p += 32) rowtab[p] = -1;
    }
    if (t < T) __stcs(&out[maskbase + t], (t >= cntF) ? 1.0f : 0.0f);
    __syncthreads();

    const float4* tab4 = (const float4*)g_tab;
    float4* o4 = (float4*)(out + pebase);
    int tot4 = T * 48;
    for (int j = t; j < tot4; j += blockDim.x) {
        int tt = j / 48, f4 = j - 48 * tt;
        int tb = rowtab[tt];
        float4 v = (tb >= 0) ? __ldg(&tab4[tb * 48 + f4]) : make_float4(0.f, 0.f, 0.f, 0.f);
        __stcs(&o4[j], v);
    }
}

// ---------------------------------------------------------------------------
extern "C" void kernel_launch(void* const* d_in, const int* in_sizes, int n_in,
                              void* d_out, int out_size) {
    const float* feats  = (const float*)d_in[0];
    const int*   coords = (const int*)d_in[1];
    float* out = (float*)d_out;

    int n = in_sizes[1] / 4;
    if (n > NV) n = NV;
    if (n <= 0) return;
    int nb = (n + 255) / 256;
    int wb = (WMAX + 7) / 8;     // 8 warps / block for per-window sort kernels

    k_tab<<<(400 * 192 + 255) / 256, 256>>>();        // LUT + zero counters
    k_wins<<<nb, 256>>>(coords, n);
    k_scanscat<<<2 + (n + 1023) / 1024, 1024>>>(n);   // fused dual-scan + scatter
    k_sw0<<<wb, 256>>>();
    k_sw1<<<wb, 256>>>();

    int featBlocks = (n * 48 + 255) / 256;
    k_write<<<2 + featBlocks + 2 * WMAX, 256>>>((const float4*)feats, coords, out,
                                                featBlocks, n);
}

// round 15
// speedup vs baseline: 1.5851x; 1.5851x over previous
#include <cuda_runtime.h>

// ---------------------------------------------------------------------------
// SparseWindowPartitionLayer — full GPU pipeline, graph-capturable, no CUB.
//   win id < 16810; T=16/32/48 by pre-drop window count; FEAT_DIM=192
//   pe depends only on in-window coords => 400-row LUT (L2 resident)
//   Stable per-window order: rank-from-histogram scatter (NO scatter atomics),
//   then per-window warp bitonic sort by original voxel index.
//   Drops need pre-drop cnt>48 (≈5σ at λ≈23) => almost never. Dropped voxel
//   ids go to a tiny list; the feats writer maps pos->src by least-fixpoint
//   over that list (identity when empty). No global compaction pass.
//   meta runs as its own tiny 2-block launch (NOT fused into the bandwidth
//   writer — R13 showed that fusion taxes the writer's registers/occupancy).
// ---------------------------------------------------------------------------

#define NV    300000
#define WMAX  16810
#define DCAP  4096

__device__ int2 g_W[NV];                        // (w0, w1)
__device__ int  g_tb[NV];                       // tb0 | tb1<<16
__device__ int2 g_rank[NV];                     // (rank in w0, rank in w1-spec)
__device__ int  g_arrA[NV], g_arrB[NV];         // window-grouped voxel ids
__device__ int  g_keepF[NV];
__device__ int  g_cnt0[WMAX], g_cnt1[WMAX];     // cnt1 = speculative (pre-drop)
__device__ int  g_cnt1c[WMAX], g_cntF0[WMAX];   // corrected counts
__device__ int  g_startA[WMAX], g_startB[WMAX]; // pure exclusive scans
__device__ int  g_lvl0[WMAX], g_lvl1[WMAX], g_conti0[WMAX], g_conti1[WMAX];
__device__ int  g_nwin[6], g_total, g_done, g_scanDone;
__device__ int  g_dropCnt, g_dropList[DCAP];
__device__ long long g_off[16];
__device__ float g_tab[400 * 192];

__device__ __forceinline__ int targetOf(int c) { return c < 16 ? 16 : (c < 32 ? 32 : 48); }
__device__ __forceinline__ int levelOf(int c)  { return c < 16 ? 0  : (c < 32 ? 1  : 2);  }
__device__ __forceinline__ int tokensOf(int l) { return l == 2 ? 48 : (16 << l); }

// ---- pe LUT + zero counters/status -------------------------------------------
__global__ void k_tab() {
    int t = blockIdx.x * blockDim.x + threadIdx.x;
    if (t < WMAX) { g_cnt0[t] = 0; g_cnt1[t] = 0; }
    if (t == 0)   { g_done = 0; g_scanDone = 0; g_dropCnt = 0; }
    if (t >= 400 * 192) return;
    int row = t / 192, f = t - 192 * row;
    int cx = row % 10, cy = (row / 10) % 10, cz = row / 100;
    int axis = f / 64, k = f - 64 * axis;
    int j = k >> 1, ph = k & 1;
    float v = (axis == 0) ? (float)(cx - 5)
            : (axis == 1) ? (float)(cy - 5)
                          : (float)(cz - 2);
    float invf = (float)exp(log(1000.0) * (double)j / 32.0);
    float e = v / invf;
    g_tab[t] = ph ? cosf(e) : sinf(e);
}

// ---- window ids + histograms + ranks + tb + keepF ------------------------------
__global__ void k_wins(const int* __restrict__ coords, int n) {
    int i = blockIdx.x * blockDim.x + threadIdx.x;
    if (i >= n) return;
    int4 c = ((const int4*)coords)[i];      // (b, z, y, x)
    int b = c.x, z = c.y, y = c.z, x = c.w;
    int w0 = b * 8405 + ((x + 10) / 10) * 205 + ((y + 10) / 10) * 5 + ((z + 4) / 4);
    int w1 = b * 8405 + ((x + 5)  / 10) * 205 + ((y + 5)  / 10) * 5 + ((z + 2) / 4);
    g_W[i] = make_int2(w0, w1);
    int tb0 = ((z % 4) * 10 + (y % 10)) * 10 + (x % 10);
    int tb1 = (((z + 2) % 4) * 10 + ((y + 5) % 10)) * 10 + ((x + 5) % 10);
    g_tb[i] = tb0 | (tb1 << 16);
    g_keepF[i] = 1;
    int r0 = atomicAdd(&g_cnt0[w0], 1);
    int r1 = atomicAdd(&g_cnt1[w1], 1);     // speculative rank (pre-drop)
    g_rank[i] = make_int2(r0, r1);
}

// ---- 1024-thread exclusive scan over WMAX counters (+input copy) ----------------
__device__ void exscan_body(const int* __restrict__ in, int* __restrict__ out,
                            int* __restrict__ cpy) {
    __shared__ int ws[32];
    int tid = threadIdx.x, lane = tid & 31, warp = tid >> 5;
    int carry = 0;
    for (int base = 0; base < WMAX; base += 1024) {
        int w = base + tid;
        int v = (w < WMAX) ? in[w] : 0;
        if (w < WMAX) cpy[w] = v;
        int x = v;
        #pragma unroll
        for (int o = 1; o < 32; o <<= 1) { int y = __shfl_up_sync(~0u, x, o); if (lane >= o) x += y; }
        if (lane == 31) ws[warp] = x;
        __syncthreads();
        if (warp == 0) {
            int y = ws[lane];
            #pragma unroll
            for (int o = 1; o < 32; o <<= 1) { int z = __shfl_up_sync(~0u, y, o); if (lane >= o) y += z; }
            ws[lane] = y;
        }
        __syncthreads();
        int excl = x - v + (warp ? ws[warp - 1] : 0) + carry;
        if (w < WMAX) out[w] = excl;
        carry += ws[31];
        __syncthreads();
    }
}

// ---- fused: blocks 0,1 = dual exscan (producers); rest = scatter (consumers) ----
__global__ void k_scanscat(int n) {
    if (blockIdx.x < 2) {
        if (blockIdx.x == 0) exscan_body(g_cnt0, g_startA, g_cntF0);
        else                 exscan_body(g_cnt1, g_startB, g_cnt1c);
        __syncthreads();
        if (threadIdx.x == 0) {
            __threadfence();
            atomicAdd(&g_scanDone, 1);
        }
        return;
    }
    int i = (blockIdx.x - 2) * blockDim.x + threadIdx.x;
    int2 w = make_int2(0, 0), r = make_int2(0, 0);
    bool valid = (i < n);
    if (valid) { w = g_W[i]; r = g_rank[i]; }   // prefetch overlaps the scans
    if (threadIdx.x == 0) {
        while (atomicAdd(&g_scanDone, 0) < 2) __nanosleep(200);
    }
    __syncthreads();
    __threadfence();                            // acquire scan outputs
    if (valid) {
        g_arrA[g_startA[w.x] + r.x] = i;
        g_arrB[g_startB[w.y] + r.y] = i;
    }
}

// ---- register bitonic sort over 32*R elements ------------------------------------
template <int R>
__device__ __forceinline__ void bitonicReg(int (&v)[R], int lane) {
    const int NE = 32 * R;
    #pragma unroll
    for (int k = 2; k <= NE; k <<= 1) {
        #pragma unroll
        for (int j = k >> 1; j > 0; j >>= 1) {
            if (j >= 32) {
                int s = j >> 5;
                #pragma unroll
                for (int r = 0; r < R; r++) {
                    int pr = r ^ s;
                    if (r < pr) {
                        bool up = (((lane + 32 * r) & k) == 0);
                        int x = v[r], y = v[pr];
                        int lo = min(x, y), hi = max(x, y);
                        v[r]  = up ? lo : hi;
                        v[pr] = up ? hi : lo;
                    }
                }
            } else {
                #pragma unroll
                for (int r = 0; r < R; r++) {
                    int e = lane + 32 * r;
                    bool up = ((e & k) == 0);
                    int o = __shfl_xor_sync(~0u, v[r], j);
                    bool lower = ((lane & j) == 0);
                    int mn = min(v[r], o), mx = max(v[r], o);
                    v[r] = (up == lower) ? mn : mx;
                }
            }
        }
    }
}

template <int R>
__device__ __forceinline__ void sortReg(int* a, int cnt, int lane) {
    int v[R];
    #pragma unroll
    for (int r = 0; r < R; r++) {
        int e = lane + 32 * r;
        v[r] = (e < cnt) ? a[e] : 0x7FFFFFFF;
    }
    // fast path: skip network + store when already sorted
    bool ok = true;
    #pragma unroll
    for (int r = 0; r < R; r++) {
        int p = __shfl_up_sync(~0u, v[r], 1);
        if (lane > 0) ok &= (v[r] >= p);
        if (r > 0) {
            int l31 = __shfl_sync(~0u, v[r - 1], 31);
            if (lane == 0) ok &= (v[r] >= l31);
        }
    }
    if (__all_sync(~0u, ok)) return;
    bitonicReg<R>(v, lane);
    #pragma unroll
    for (int r = 0; r < R; r++) {
        int e = lane + 32 * r;
        if (e < cnt) a[e] = v[r];
    }
}

__device__ void sortSeg(int* a, int cnt, int lane) {
    if (cnt <= 32)       sortReg<1>(a, cnt, lane);
    else if (cnt <= 64)  sortReg<2>(a, cnt, lane);
    else if (cnt <= 128) sortReg<4>(a, cnt, lane);
    else {
        // robust fallback (not expected for this dataset): odd-even transposition
        for (int pass = 0; pass < cnt; pass++) {
            for (int p = (pass & 1) + 2 * lane; p + 1 < cnt; p += 64) {
                int x = a[p], y = a[p + 1];
                if (x > y) { a[p] = y; a[p + 1] = x; }
            }
            __syncwarp();
            __threadfence_block();
        }
    }
    __syncwarp();
}

// ---- shift-0 sort; drops: flag+list, fix counts, sentinel the arrB slot ----------
__global__ void k_sw0() {
    int wid = blockIdx.x * (blockDim.x >> 5) + (threadIdx.x >> 5);
    if (wid >= WMAX) return;
    int lane = threadIdx.x & 31;
    int cnt = g_cnt0[wid];
    if (cnt == 0) return;
    int seg = g_startA[wid];
    sortSeg(g_arrA + seg, cnt, lane);
    int t = targetOf(cnt);
    for (int e = t + lane; e < cnt; e += 32) {   // drops only (rare)
        int v = g_arrA[seg + e];
        g_keepF[v] = 0;
        int slot = atomicAdd(&g_dropCnt, 1);
        if (slot < DCAP) g_dropList[slot] = v;
        int w1 = g_W[v].y;
        atomicSub(&g_cnt1c[w1], 1);
        atomicSub(&g_cntF0[wid], 1);
        g_arrB[g_startB[w1] + g_rank[v].y] = 0x7FFFFFFF;  // sentinel
    }
}

// ---- shift-1 sort (sentinels go to tail); drops among first cnt1c entries --------
__global__ void k_sw1() {
    int wid = blockIdx.x * (blockDim.x >> 5) + (threadIdx.x >> 5);
    if (wid >= WMAX) return;
    int lane = threadIdx.x & 31;
    int spec = g_cnt1[wid];
    if (spec == 0) return;
    int seg = g_startB[wid];
    sortSeg(g_arrB + seg, spec, lane);
    int cnt = g_cnt1c[wid];                      // exact kept0 count
    int t = targetOf(cnt);
    for (int e = t + lane; e < cnt; e += 32) {   // drops only (rare)
        int v = g_arrB[seg + e];
        g_keepF[v] = 0;
        int slot = atomicAdd(&g_dropCnt, 1);
        if (slot < DCAP) g_dropList[slot] = v;
        atomicSub(&g_cntF0[g_W[v].x], 1);
    }
}

// ---- meta launch (2 blocks, one per shift): lvl/conti, nwin, total, offsets ------
__global__ void k_meta() {
    int s = blockIdx.x;
    __shared__ int sh0[8], sh1[8], sh2[8], sh3[8];
    int tid = threadIdx.x, lane = tid & 31, warp = tid >> 5;
    int* lvlArr  = s ? g_lvl1   : g_lvl0;
    int* contArr = s ? g_conti1 : g_conti0;
    int c0 = 0, c1 = 0, c2 = 0, c3 = 0;
    for (int base = 0; base < WMAX; base += 1024) {
        int cf[4], lv[4], f1[4], f2[4], f3[4];
        #pragma unroll
        for (int k = 0; k < 4; k++) {
            int w = base + tid * 4 + k;
            cf[k] = 0; lv[k] = 0;
            if (w < WMAX) {
                if (s == 0) { cf[k] = g_cntF0[w]; lv[k] = levelOf(g_cnt0[w]); }
                else        { int c = g_cnt1c[w]; cf[k] = min(c, targetOf(c)); lv[k] = levelOf(c); }
            }
            int occ = cf[k] > 0;
            f1[k] = (occ && lv[k] == 0) ? 1 : 0;
            f2[k] = (occ && lv[k] == 1) ? 1 : 0;
            f3[k] = (occ && lv[k] == 2) ? 1 : 0;
        }
        int t0 = cf[0] + cf[1] + cf[2] + cf[3];
        int t1 = f1[0] + f1[1] + f1[2] + f1[3];
        int t2 = f2[0] + f2[1] + f2[2] + f2[3];
        int t3 = f3[0] + f3[1] + f3[2] + f3[3];
        int x0 = t0, x1 = t1, x2 = t2, x3 = t3;
        #pragma unroll
        for (int o = 1; o < 32; o <<= 1) {
            int y0 = __shfl_up_sync(~0u, x0, o);
            int y1 = __shfl_up_sync(~0u, x1, o);
            int y2 = __shfl_up_sync(~0u, x2, o);
            int y3 = __shfl_up_sync(~0u, x3, o);
            if (lane >= o) { x0 += y0; x1 += y1; x2 += y2; x3 += y3; }
        }
        if (lane == 31) { sh0[warp] = x0; sh1[warp] = x1; sh2[warp] = x2; sh3[warp] = x3; }
        __syncthreads();
        if (tid < 8) {
            int y0 = sh0[tid], y1 = sh1[tid], y2 = sh2[tid], y3 = sh3[tid];
            #pragma unroll
            for (int o = 1; o < 8; o <<= 1) {
                int z0 = __shfl_up_sync(0xFFu, y0, o);
                int z1 = __shfl_up_sync(0xFFu, y1, o);
                int z2 = __shfl_up_sync(0xFFu, y2, o);
                int z3 = __shfl_up_sync(0xFFu, y3, o);
                if (tid >= o) { y0 += z0; y1 += z1; y2 += z2; y3 += z3; }
            }
            sh0[tid] = y0; sh1[tid] = y1; sh2[tid] = y2; sh3[tid] = y3;
        }
        __syncthreads();
        int b1 = x1 - t1 + (warp ? sh1[warp - 1] : 0) + c1;
        int b2 = x2 - t2 + (warp ? sh2[warp - 1] : 0) + c2;
        int b3 = x3 - t3 + (warp ? sh3[warp - 1] : 0) + c3;
        #pragma unroll
        for (int k = 0; k < 4; k++) {
            int w = base + tid * 4 + k;
            if (w < WMAX) {
                lvlArr[w]  = lv[k];
                contArr[w] = (lv[k] == 0) ? b1 : (lv[k] == 1) ? b2 : b3;
            }
            b1 += f1[k]; b2 += f2[k]; b3 += f3[k];
        }
        c0 += sh0[7]; c1 += sh1[7]; c2 += sh2[7]; c3 += sh3[7];
        __syncthreads();
    }
    if (tid == 0) {
        g_nwin[3 * s + 0] = c1;
        g_nwin[3 * s + 1] = c2;
        g_nwin[3 * s + 2] = c3;
        if (s == 0) g_total = c0;
        __threadfence();
        int prev = atomicAdd(&g_done, 1);
        if (prev == 1) {                       // second finisher computes offsets
            __threadfence();
            long long M = *((volatile int*)&g_total);
            int nw[6];
            #pragma unroll
            for (int q = 0; q < 6; q++) nw[q] = *((volatile int*)&g_nwin[q]);
            long long o = 0;
            g_off[0] = 0;       o = M * 192;          // feats
            g_off[1] = o;       o += M * 4;           // coords
            const int T[3] = {16, 32, 48};
            for (int ss = 0; ss < 2; ss++) {
                for (int d = 0; d < 3; d++) { g_off[2 + 6 * ss + d] = o; o += (long long)nw[3 * ss + d] * T[d] * 192; }
                for (int d = 0; d < 3; d++) { g_off[5 + 6 * ss + d] = o; o += (long long)nw[3 * ss + d] * T[d]; }
            }
            g_off[14] = o;
        }
    }
}

// ---- fused writer: feats+coords gather (first featBlocks) then pe+mask -----------
__global__ void k_write(const float4* __restrict__ fin, const int* __restrict__ coords,
                        float* __restrict__ out, int featBlocks, int n) {
    if ((int)blockIdx.x < featBlocks) {
        // ---- feats + coords: pos->src via tiny drop list (identity when empty)
        int d = g_dropCnt;                      // final before this launch
        if (d > DCAP) d = DCAP;
        int M = n - d;
        int idx = blockIdx.x * blockDim.x + threadIdx.x;
        int pos = idx / 48, c = idx - 48 * pos;
        if (pos >= M) return;
        int src = pos;
        if (d > 0) {                            // least fixpoint src = pos + |D<=src|
            int prev = -1;
            while (src != prev) {
                prev = src;
                int cdl = 0;
                for (int q = 0; q < d; q++) cdl += (g_dropList[q] <= src);
                src = pos + cdl;
            }
        }
        float4 v = __ldcs(&fin[(long long)src * 48 + c]);
        __stcs(&((float4*)out)[(long long)pos * 48 + c], v);
        if (c == 0) {
            int4 cc = ((const int4*)coords)[src];
            float4* oc = (float4*)(out + g_off[1]);
            __stcs(&oc[pos], make_float4((float)cc.x, (float)cc.y, (float)cc.z, (float)cc.w));
        }
        return;
    }

    // ---- pe + mask: one block per (shift, window)
    int b = (int)blockIdx.x - featBlocks;      // [0, 2*WMAX)
    int s = (b >= WMAX) ? 1 : 0;
    int w = b - s * WMAX;

    int cntSeg, cntF, segStart, lvl, conti;
    const int* arr;
    if (s == 0) {
        cntSeg = g_cnt0[w];
        cntF   = g_cntF0[w];
        if (cntF == 0) return;
        segStart = g_startA[w];
        lvl = g_lvl0[w]; conti = g_conti0[w];
        arr = g_arrA;
    } else {
        int cnt = g_cnt1c[w];
        if (cnt <= 0) return;
        cntF = min(cnt, targetOf(cnt));
        segStart = g_startB[w];
        lvl = g_lvl1[w]; conti = g_conti1[w];
        arr = g_arrB;
        cntSeg = cntF;        // first cntF sorted entries are the kept set
    }
    int T = tokensOf(lvl);
    long long pebase   = g_off[2 + 6 * s + lvl] + (long long)conti * T * 192;
    long long maskbase = g_off[5 + 6 * s + lvl] + (long long)conti * T;

    __shared__ int rowtab[48];
    int t = threadIdx.x;
    if (t < 32) {
        int lane = t;
        int nk = 0;
        for (int base = 0; base < cntSeg; base += 32) {
            int r = base + lane;
            int v = (r < cntSeg) ? arr[segStart + r] : -1;
            int f = (v >= 0) ? ((s == 0) ? g_keepF[v] : 1) : 0;
            unsigned m = __ballot_sync(~0u, f);
            if (f) {
                int slot = nk + __popc(m & ((1u << lane) - 1));
                int tb = g_tb[v];
                rowtab[slot] = s ? (tb >> 16) : (tb & 0xFFFF);
            }
            nk += __popc(m);
        }
        for (int p = nk + lane; p < T; p += 32) rowtab[p] = -1;
    }
    if (t < T) __stcs(&out[maskbase + t], (t >= cntF) ? 1.0f : 0.0f);
    __syncthreads();

    const float4* tab4 = (const float4*)g_tab;
    float4* o4 = (float4*)(out + pebase);
    int tot4 = T * 48;
    for (int j = t; j < tot4; j += blockDim.x) {
        int tt = j / 48, f4 = j - 48 * tt;
        int tb = rowtab[tt];
        float4 v = (tb >= 0) ? __ldg(&tab4[tb * 48 + f4]) : make_float4(0.f, 0.f, 0.f, 0.f);
        __stcs(&o4[j], v);
    }
}

// ---------------------------------------------------------------------------
extern "C" void kernel_launch(void* const* d_in, const int* in_sizes, int n_in,
                              void* d_out, int out_size) {
    const float* feats  = (const float*)d_in[0];
    const int*   coords = (const int*)d_in[1];
    float* out = (float*)d_out;

    int n = in_sizes[1] / 4;
    if (n > NV) n = NV;
    if (n <= 0) return;
    int nb = (n + 255) / 256;
    int wb = (WMAX + 7) / 8;     // 8 warps / block for per-window sort kernels

    k_tab<<<(400 * 192 + 255) / 256, 256>>>();        // LUT + zero counters
    k_wins<<<nb, 256>>>(coords, n);
    k_scanscat<<<2 + (n + 1023) / 1024, 1024>>>(n);   // fused dual-scan + scatter
    k_sw0<<<wb, 256>>>();
    k_sw1<<<wb, 256>>>();
    k_meta<<<2, 256>>>();

    int featBlocks = (n * 48 + 255) / 256;
    k_write<<<featBlocks + 2 * WMAX, 256>>>((const float4*)feats, coords, out,
                                            featBlocks, n);
}

// round 16
// speedup vs baseline: 1.6529x; 1.0428x over previous
#include <cuda_runtime.h>

// ---------------------------------------------------------------------------
// SparseWindowPartitionLayer — full GPU pipeline, graph-capturable, no CUB.
//   win id < 16810; T=16/32/48 by pre-drop window count; FEAT_DIM=192
//   pe depends only on in-window coords => 400-row LUT (L2 resident)
//   Stable per-window order: rank-from-histogram scatter (NO scatter atomics),
//   then per-window warp bitonic sort. Sorted entries are PACKED (idx<<9|tb):
//   packed order == index order, and pe reads its row table straight from the
//   sorted segment (no random tb gather).
//   Drops need pre-drop cnt>48 (≈5σ at λ≈23) => almost never. Dropped voxel
//   ids go to a tiny list; feats maps pos->src by least-fixpoint over it
//   (identity when empty); pe uses a drop-free fast path when dropCnt==0.
// ---------------------------------------------------------------------------

#define NV    300000
#define WMAX  16810
#define DCAP  4096

__device__ int2 g_W[NV];                        // (w0, w1)
__device__ int  g_tb[NV];                       // tb0 | tb1<<16
__device__ int2 g_rank[NV];                     // (rank in w0, rank in w1-spec)
__device__ int  g_arrA[NV], g_arrB[NV];         // packed (idx<<9 | tb) per window
__device__ int  g_keepF[NV];
__device__ int  g_cnt0[WMAX], g_cnt1[WMAX];     // cnt1 = speculative (pre-drop)
__device__ int  g_cnt1c[WMAX], g_cntF0[WMAX];   // corrected counts
__device__ int  g_startA[WMAX], g_startB[WMAX]; // pure exclusive scans
__device__ int  g_lvl0[WMAX], g_lvl1[WMAX], g_conti0[WMAX], g_conti1[WMAX];
__device__ int  g_nwin[6], g_total, g_done, g_scanDone;
__device__ int  g_dropCnt, g_dropList[DCAP];
__device__ long long g_off[16];
__device__ float g_tab[400 * 192];

__device__ __forceinline__ int targetOf(int c) { return c < 16 ? 16 : (c < 32 ? 32 : 48); }
__device__ __forceinline__ int levelOf(int c)  { return c < 16 ? 0  : (c < 32 ? 1  : 2);  }
__device__ __forceinline__ int tokensOf(int l) { return l == 2 ? 48 : (16 << l); }

// ---- pe LUT + zero counters/status -------------------------------------------
__global__ void k_tab() {
    int t = blockIdx.x * blockDim.x + threadIdx.x;
    if (t < WMAX) { g_cnt0[t] = 0; g_cnt1[t] = 0; }
    if (t == 0)   { g_done = 0; g_scanDone = 0; g_dropCnt = 0; }
    if (t >= 400 * 192) return;
    int row = t / 192, f = t - 192 * row;
    int cx = row % 10, cy = (row / 10) % 10, cz = row / 100;
    int axis = f / 64, k = f - 64 * axis;
    int j = k >> 1, ph = k & 1;
    float v = (axis == 0) ? (float)(cx - 5)
            : (axis == 1) ? (float)(cy - 5)
                          : (float)(cz - 2);
    float invf = (float)exp(log(1000.0) * (double)j / 32.0);
    float e = v / invf;
    g_tab[t] = ph ? cosf(e) : sinf(e);
}

// ---- window ids + histograms + ranks + tb + keepF ------------------------------
__global__ void k_wins(const int* __restrict__ coords, int n) {
    int i = blockIdx.x * blockDim.x + threadIdx.x;
    if (i >= n) return;
    int4 c = ((const int4*)coords)[i];      // (b, z, y, x)
    int b = c.x, z = c.y, y = c.z, x = c.w;
    int w0 = b * 8405 + ((x + 10) / 10) * 205 + ((y + 10) / 10) * 5 + ((z + 4) / 4);
    int w1 = b * 8405 + ((x + 5)  / 10) * 205 + ((y + 5)  / 10) * 5 + ((z + 2) / 4);
    g_W[i] = make_int2(w0, w1);
    int tb0 = ((z % 4) * 10 + (y % 10)) * 10 + (x % 10);
    int tb1 = (((z + 2) % 4) * 10 + ((y + 5) % 10)) * 10 + ((x + 5) % 10);
    g_tb[i] = tb0 | (tb1 << 16);
    g_keepF[i] = 1;
    int r0 = atomicAdd(&g_cnt0[w0], 1);
    int r1 = atomicAdd(&g_cnt1[w1], 1);     // speculative rank (pre-drop)
    g_rank[i] = make_int2(r0, r1);
}

// ---- 1024-thread exclusive scan over WMAX counters (+input copy) ----------------
__device__ void exscan_body(const int* __restrict__ in, int* __restrict__ out,
                            int* __restrict__ cpy) {
    __shared__ int ws[32];
    int tid = threadIdx.x, lane = tid & 31, warp = tid >> 5;
    int carry = 0;
    for (int base = 0; base < WMAX; base += 1024) {
        int w = base + tid;
        int v = (w < WMAX) ? in[w] : 0;
        if (w < WMAX) cpy[w] = v;
        int x = v;
        #pragma unroll
        for (int o = 1; o < 32; o <<= 1) { int y = __shfl_up_sync(~0u, x, o); if (lane >= o) x += y; }
        if (lane == 31) ws[warp] = x;
        __syncthreads();
        if (warp == 0) {
            int y = ws[lane];
            #pragma unroll
            for (int o = 1; o < 32; o <<= 1) { int z = __shfl_up_sync(~0u, y, o); if (lane >= o) y += z; }
            ws[lane] = y;
        }
        __syncthreads();
        int excl = x - v + (warp ? ws[warp - 1] : 0) + carry;
        if (w < WMAX) out[w] = excl;
        carry += ws[31];
        __syncthreads();
    }
}

// ---- fused: blocks 0,1 = dual exscan (producers); rest = scatter (consumers) ----
__global__ void k_scanscat(int n) {
    if (blockIdx.x < 2) {
        if (blockIdx.x == 0) exscan_body(g_cnt0, g_startA, g_cntF0);
        else                 exscan_body(g_cnt1, g_startB, g_cnt1c);
        __syncthreads();
        if (threadIdx.x == 0) {
            __threadfence();
            atomicAdd(&g_scanDone, 1);
        }
        return;
    }
    int i = (blockIdx.x - 2) * blockDim.x + threadIdx.x;
    int2 w = make_int2(0, 0), r = make_int2(0, 0);
    int tb = 0;
    bool valid = (i < n);
    if (valid) { w = g_W[i]; r = g_rank[i]; tb = g_tb[i]; }  // prefetch over scans
    if (threadIdx.x == 0) {
        while (atomicAdd(&g_scanDone, 0) < 2) __nanosleep(200);
    }
    __syncthreads();
    __threadfence();                            // acquire scan outputs
    if (valid) {
        g_arrA[g_startA[w.x] + r.x] = (i << 9) | (tb & 0x1FF);
        g_arrB[g_startB[w.y] + r.y] = (i << 9) | (tb >> 16);
    }
}

// ---- register bitonic sort over 32*R elements ------------------------------------
template <int R>
__device__ __forceinline__ void bitonicReg(int (&v)[R], int lane) {
    const int NE = 32 * R;
    #pragma unroll
    for (int k = 2; k <= NE; k <<= 1) {
        #pragma unroll
        for (int j = k >> 1; j > 0; j >>= 1) {
            if (j >= 32) {
                int s = j >> 5;
                #pragma unroll
                for (int r = 0; r < R; r++) {
                    int pr = r ^ s;
                    if (r < pr) {
                        bool up = (((lane + 32 * r) & k) == 0);
                        int x = v[r], y = v[pr];
                        int lo = min(x, y), hi = max(x, y);
                        v[r]  = up ? lo : hi;
                        v[pr] = up ? hi : lo;
                    }
                }
            } else {
                #pragma unroll
                for (int r = 0; r < R; r++) {
                    int e = lane + 32 * r;
                    bool up = ((e & k) == 0);
                    int o = __shfl_xor_sync(~0u, v[r], j);
                    bool lower = ((lane & j) == 0);
                    int mn = min(v[r], o), mx = max(v[r], o);
                    v[r] = (up == lower) ? mn : mx;
                }
            }
        }
    }
}

template <int R>
__device__ __forceinline__ void sortReg(int* a, int cnt, int lane) {
    int v[R];
    #pragma unroll
    for (int r = 0; r < R; r++) {
        int e = lane + 32 * r;
        v[r] = (e < cnt) ? a[e] : 0x7FFFFFFF;
    }
    bitonicReg<R>(v, lane);
    #pragma unroll
    for (int r = 0; r < R; r++) {
        int e = lane + 32 * r;
        if (e < cnt) a[e] = v[r];
    }
}

__device__ void sortSeg(int* a, int cnt, int lane) {
    if (cnt <= 32)       sortReg<1>(a, cnt, lane);
    else if (cnt <= 64)  sortReg<2>(a, cnt, lane);
    else if (cnt <= 128) sortReg<4>(a, cnt, lane);
    else {
        // robust fallback (not expected for this dataset): odd-even transposition
        for (int pass = 0; pass < cnt; pass++) {
            for (int p = (pass & 1) + 2 * lane; p + 1 < cnt; p += 64) {
                int x = a[p], y = a[p + 1];
                if (x > y) { a[p] = y; a[p + 1] = x; }
            }
            __syncwarp();
            __threadfence_block();
        }
    }
    __syncwarp();
}

// ---- shift-0 sort; drops: flag+list, fix counts, sentinel the arrB slot ----------
__global__ void __launch_bounds__(256, 8) k_sw0() {
    int wid = blockIdx.x * (blockDim.x >> 5) + (threadIdx.x >> 5);
    if (wid >= WMAX) return;
    int lane = threadIdx.x & 31;
    int cnt = g_cnt0[wid];
    if (cnt == 0) return;
    int seg = g_startA[wid];
    sortSeg(g_arrA + seg, cnt, lane);
    int t = targetOf(cnt);
    for (int e = t + lane; e < cnt; e += 32) {   // drops only (rare)
        int v = g_arrA[seg + e] >> 9;
        g_keepF[v] = 0;
        int slot = atomicAdd(&g_dropCnt, 1);
        if (slot < DCAP) g_dropList[slot] = v;
        int w1 = g_W[v].y;
        atomicSub(&g_cnt1c[w1], 1);
        atomicSub(&g_cntF0[wid], 1);
        g_arrB[g_startB[w1] + g_rank[v].y] = 0x7FFFFFFF;  // sentinel (max packed)
    }
}

// ---- shift-1 sort (sentinels go to tail); drops among first cnt1c entries --------
__global__ void __launch_bounds__(256, 8) k_sw1() {
    int wid = blockIdx.x * (blockDim.x >> 5) + (threadIdx.x >> 5);
    if (wid >= WMAX) return;
    int lane = threadIdx.x & 31;
    int spec = g_cnt1[wid];
    if (spec == 0) return;
    int seg = g_startB[wid];
    sortSeg(g_arrB + seg, spec, lane);
    int cnt = g_cnt1c[wid];                      // exact kept0 count
    int t = targetOf(cnt);
    for (int e = t + lane; e < cnt; e += 32) {   // drops only (rare)
        int v = g_arrB[seg + e] >> 9;
        g_keepF[v] = 0;
        int slot = atomicAdd(&g_dropCnt, 1);
        if (slot < DCAP) g_dropList[slot] = v;
        atomicSub(&g_cntF0[g_W[v].x], 1);
    }
}

// ---- meta launch (2 blocks, one per shift): lvl/conti, nwin, total, offsets ------
__global__ void k_meta() {
    int s = blockIdx.x;
    __shared__ int sh0[8], sh1[8], sh2[8], sh3[8];
    int tid = threadIdx.x, lane = tid & 31, warp = tid >> 5;
    int* lvlArr  = s ? g_lvl1   : g_lvl0;
    int* contArr = s ? g_conti1 : g_conti0;
    int c0 = 0, c1 = 0, c2 = 0, c3 = 0;
    for (int base = 0; base < WMAX; base += 1024) {
        int cf[4], lv[4], f1[4], f2[4], f3[4];
        #pragma unroll
        for (int k = 0; k < 4; k++) {
            int w = base + tid * 4 + k;
            cf[k] = 0; lv[k] = 0;
            if (w < WMAX) {
                if (s == 0) { cf[k] = g_cntF0[w]; lv[k] = levelOf(g_cnt0[w]); }
                else        { int c = g_cnt1c[w]; cf[k] = min(c, targetOf(c)); lv[k] = levelOf(c); }
            }
            int occ = cf[k] > 0;
            f1[k] = (occ && lv[k] == 0) ? 1 : 0;
            f2[k] = (occ && lv[k] == 1) ? 1 : 0;
            f3[k] = (occ && lv[k] == 2) ? 1 : 0;
        }
        int t0 = cf[0] + cf[1] + cf[2] + cf[3];
        int t1 = f1[0] + f1[1] + f1[2] + f1[3];
        int t2 = f2[0] + f2[1] + f2[2] + f2[3];
        int t3 = f3[0] + f3[1] + f3[2] + f3[3];
        int x0 = t0, x1 = t1, x2 = t2, x3 = t3;
        #pragma unroll
        for (int o = 1; o < 32; o <<= 1) {
            int y0 = __shfl_up_sync(~0u, x0, o);
            int y1 = __shfl_up_sync(~0u, x1, o);
            int y2 = __shfl_up_sync(~0u, x2, o);
            int y3 = __shfl_up_sync(~0u, x3, o);
            if (lane >= o) { x0 += y0; x1 += y1; x2 += y2; x3 += y3; }
        }
        if (lane == 31) { sh0[warp] = x0; sh1[warp] = x1; sh2[warp] = x2; sh3[warp] = x3; }
        __syncthreads();
        if (tid < 8) {
            int y0 = sh0[tid], y1 = sh1[tid], y2 = sh2[tid], y3 = sh3[tid];
            #pragma unroll
            for (int o = 1; o < 8; o <<= 1) {
                int z0 = __shfl_up_sync(0xFFu, y0, o);
                int z1 = __shfl_up_sync(0xFFu, y1, o);
                int z2 = __shfl_up_sync(0xFFu, y2, o);
                int z3 = __shfl_up_sync(0xFFu, y3, o);
                if (tid >= o) { y0 += z0; y1 += z1; y2 += z2; y3 += z3; }
            }
            sh0[tid] = y0; sh1[tid] = y1; sh2[tid] = y2; sh3[tid] = y3;
        }
        __syncthreads();
        int b1 = x1 - t1 + (warp ? sh1[warp - 1] : 0) + c1;
        int b2 = x2 - t2 + (warp ? sh2[warp - 1] : 0) + c2;
        int b3 = x3 - t3 + (warp ? sh3[warp - 1] : 0) + c3;
        #pragma unroll
        for (int k = 0; k < 4; k++) {
            int w = base + tid * 4 + k;
            if (w < WMAX) {
                lvlArr[w]  = lv[k];
                contArr[w] = (lv[k] == 0) ? b1 : (lv[k] == 1) ? b2 : b3;
            }
            b1 += f1[k]; b2 += f2[k]; b3 += f3[k];
        }
        c0 += sh0[7]; c1 += sh1[7]; c2 += sh2[7]; c3 += sh3[7];
        __syncthreads();
    }
    if (tid == 0) {
        g_nwin[3 * s + 0] = c1;
        g_nwin[3 * s + 1] = c2;
        g_nwin[3 * s + 2] = c3;
        if (s == 0) g_total = c0;
        __threadfence();
        int prev = atomicAdd(&g_done, 1);
        if (prev == 1) {                       // second finisher computes offsets
            __threadfence();
            long long M = *((volatile int*)&g_total);
            int nw[6];
            #pragma unroll
            for (int q = 0; q < 6; q++) nw[q] = *((volatile int*)&g_nwin[q]);
            long long o = 0;
            g_off[0] = 0;       o = M * 192;          // feats
            g_off[1] = o;       o += M * 4;           // coords
            const int T[3] = {16, 32, 48};
            for (int ss = 0; ss < 2; ss++) {
                for (int d = 0; d < 3; d++) { g_off[2 + 6 * ss + d] = o; o += (long long)nw[3 * ss + d] * T[d] * 192; }
                for (int d = 0; d < 3; d++) { g_off[5 + 6 * ss + d] = o; o += (long long)nw[3 * ss + d] * T[d]; }
            }
            g_off[14] = o;
        }
    }
}

// ---- fused writer: feats+coords gather (first featBlocks) then pe+mask -----------
__global__ void k_write(const float4* __restrict__ fin, const int* __restrict__ coords,
                        float* __restrict__ out, int featBlocks, int n) {
    if ((int)blockIdx.x < featBlocks) {
        // ---- feats + coords: pos->src via tiny drop list (identity when empty)
        int d = g_dropCnt;                      // final before this launch
        if (d > DCAP) d = DCAP;
        int M = n - d;
        int idx = blockIdx.x * blockDim.x + threadIdx.x;
        int pos = idx / 48, c = idx - 48 * pos;
        if (pos >= M) return;
        int src = pos;
        if (d > 0) {                            // least fixpoint src = pos + |D<=src|
            int prev = -1;
            while (src != prev) {
                prev = src;
                int cdl = 0;
                for (int q = 0; q < d; q++) cdl += (g_dropList[q] <= src);
                src = pos + cdl;
            }
        }
        float4 v = __ldcs(&fin[(long long)src * 48 + c]);
        __stcs(&((float4*)out)[(long long)pos * 48 + c], v);
        if (c == 0) {
            int4 cc = ((const int4*)coords)[src];
            float4* oc = (float4*)(out + g_off[1]);
            __stcs(&oc[pos], make_float4((float)cc.x, (float)cc.y, (float)cc.z, (float)cc.w));
        }
        return;
    }

    // ---- pe + mask: one block per (shift, window)
    int b = (int)blockIdx.x - featBlocks;      // [0, 2*WMAX)
    int s = (b >= WMAX) ? 1 : 0;
    int w = b - s * WMAX;

    int cntSeg, cntF, segStart, lvl, conti;
    const int* arr;
    if (s == 0) {
        cntSeg = g_cnt0[w];
        cntF   = g_cntF0[w];
        if (cntF == 0) return;
        segStart = g_startA[w];
        lvl = g_lvl0[w]; conti = g_conti0[w];
        arr = g_arrA;
    } else {
        int cnt = g_cnt1c[w];
        if (cnt <= 0) return;
        cntF = min(cnt, targetOf(cnt));
        segStart = g_startB[w];
        lvl = g_lvl1[w]; conti = g_conti1[w];
        arr = g_arrB;
        cntSeg = cntF;        // first cntF sorted entries are the kept set
    }
    int T = tokensOf(lvl);
    long long pebase   = g_off[2 + 6 * s + lvl] + (long long)conti * T * 192;
    long long maskbase = g_off[5 + 6 * s + lvl] + (long long)conti * T;

    __shared__ int rowtab[48];
    int t = threadIdx.x;
    int d = g_dropCnt;
    if (d == 0 || s == 1) {
        // drop-free (or shift-1, where kept set == first cntF sorted entries):
        // row table comes straight from the packed sorted segment
        if (t < T) rowtab[t] = (t < cntF) ? (arr[segStart + t] & 0x1FF) : -1;
    } else if (t < 32) {
        // rare: shift-0 with drops => filter by keepF via ballot compaction
        int lane = t;
        int nk = 0;
        for (int base = 0; base < cntSeg; base += 32) {
            int r = base + lane;
            int val = (r < cntSeg) ? arr[segStart + r] : -1;
            int f = (val >= 0) ? g_keepF[val >> 9] : 0;
            unsigned m = __ballot_sync(~0u, f);
            if (f) {
                int slot = nk + __popc(m & ((1u << lane) - 1));
                rowtab[slot] = val & 0x1FF;
            }
            nk += __popc(m);
        }
        for (int p = nk + lane; p < T; p += 32) rowtab[p] = -1;
    }
    if (t < T) __stcs(&out[maskbase + t], (t >= cntF) ? 1.0f : 0.0f);
    __syncthreads();

    const float4* tab4 = (const float4*)g_tab;
    float4* o4 = (float4*)(out + pebase);
    int tot4 = T * 48;
    for (int j = t; j < tot4; j += blockDim.x) {
        int tt = j / 48, f4 = j - 48 * tt;
        int tb = rowtab[tt];
        float4 v = (tb >= 0) ? __ldg(&tab4[tb * 48 + f4]) : make_float4(0.f, 0.f, 0.f, 0.f);
        __stcs(&o4[j], v);
    }
}

// ---------------------------------------------------------------------------
extern "C" void kernel_launch(void* const* d_in, const int* in_sizes, int n_in,
                              void* d_out, int out_size) {
    const float* feats  = (const float*)d_in[0];
    const int*   coords = (const int*)d_in[1];
    float* out = (float*)d_out;

    int n = in_sizes[1] / 4;
    if (n > NV) n = NV;
    if (n <= 0) return;
    int nb = (n + 255) / 256;
    int wb = (WMAX + 7) / 8;     // 8 warps / block for per-window sort kernels

    k_tab<<<(400 * 192 + 255) / 256, 256>>>();        // LUT + zero counters
    k_wins<<<nb, 256>>>(coords, n);
    k_scanscat<<<2 + (n + 1023) / 1024, 1024>>>(n);   // fused dual-scan + scatter
    k_sw0<<<wb, 256>>>();
    k_sw1<<<wb, 256>>>();
    k_meta<<<2, 256>>>();

    int featBlocks = (n * 48 + 255) / 256;
    k_write<<<featBlocks + 2 * WMAX, 256>>>((const float4*)feats, coords, out,
                                            featBlocks, n);
}